// round 16
// baseline (speedup 1.0000x reference)
#include <cuda_runtime.h>
#include <cuda_fp16.h>
#include <stdint.h>
#include <stddef.h>

// ---------------- problem constants ----------------
#define B_    2
#define NQ_   768
#define NK_   768

// ---------------- static scratch ----------------
__device__ uint32_t g_qeh [B_*NQ_*48];      // [b,q][ch2] half2(qe[2ch2], qe[2ch2+1])
__device__ uint32_t g_keTh[B_*48*NK_];      // [b][ch2][k] half2(ke[2ch2], ke[2ch2+1])
__device__ uint32_t g_Aqh [B_*NQ_*64];      // [b,q][f2] half2 of Aq = b1 + qi@W1[0:32]
__device__ uint32_t g_Bkh [B_*NK_*64];      // [b,k][f2] half2 of Bk = ki@W1[32:64]
__device__ uint32_t g_W1h [128*36];         // [n][kq] B-tile for A=[dot|dist] (K=64)
__device__ uint32_t g_W2h [64*68];          // [n][kq] half2{W2[2kq][n], W2[2kq+1][n]}

// ---------------- helpers ----------------
__device__ __forceinline__ uint32_t smem_u32(const void* p){
    uint32_t a;
    asm("{ .reg .u64 t; cvta.to.shared.u64 t, %1; cvt.u32.u64 %0, t; }" : "=r"(a) : "l"(p));
    return a;
}
__device__ __forceinline__ float tanh_ap(float x){
    float y; asm("tanh.approx.f32 %0, %1;" : "=f"(y) : "f"(x)); return y;
}
__device__ __forceinline__ float sqrt_ap(float x){
    float y; asm("sqrt.approx.f32 %0, %1;" : "=f"(y) : "f"(x)); return y;
}
__device__ __forceinline__ float silu_f(float v){
    const float hv = 0.5f * v;
    return fmaf(hv, tanh_ap(hv), hv);          // v * sigmoid(v)
}
__device__ __forceinline__ uint32_t pack2(float a, float b){
    __half2 h = __floats2half2_rn(a, b);
    return *(const uint32_t*)&h;
}
__device__ __forceinline__ float2 unpack2(uint32_t u){
    return __half22float2(*(__half2*)&u);
}
__device__ __forceinline__ void ldmx4(uint32_t* r, uint32_t addr){
    asm volatile("ldmatrix.sync.aligned.m8n8.x4.shared.b16 {%0,%1,%2,%3}, [%4];"
        : "=r"(r[0]), "=r"(r[1]), "=r"(r[2]), "=r"(r[3]) : "r"(addr));
}
__device__ __forceinline__ void mma16816(float* d, const uint32_t* a, uint32_t b0, uint32_t b1){
    asm volatile(
        "mma.sync.aligned.m16n8k16.row.col.f32.f16.f16.f32 "
        "{%0,%1,%2,%3}, {%4,%5,%6,%7}, {%8,%9}, {%0,%1,%2,%3};"
        : "+f"(d[0]), "+f"(d[1]), "+f"(d[2]), "+f"(d[3])
        : "r"(a[0]), "r"(a[1]), "r"(a[2]), "r"(a[3]), "r"(b0), "r"(b1));
}

// ---------------- pair-kernel smem layout (bytes) ----------------
#define O_W1H  0                // [128 n][72 k] fp16, stride 144B    = 18432
#define O_W2H  18432            // [ 64 n][136 k] fp16, stride 272B   = 17408
#define O_KETH 35840            // [48 ch2][68 kk] u32 (stride 68)    = 13056
#define O_BKH  48896            // [64 kk][68 f2] u32 (stride 68)     = 17408
#define O_AQH  66304            // [16][64] u32                       = 4096
#define O_QEH  70400            // [16][48] u32                       = 3072
#define O_B2   73472            // [64] fp32                          = 256
#define O_F    73728            // 8 warps x [32 p][144B]             = 36864
#define SMEM_TOTAL 110592

// ---------------- proj-kernel smem layout (floats) ----------------
#define P_WE   0                // [256*32]                           = 8192 f
#define P_WI   8192             // [256*32]                           = 8192 f
#define P_W1S  16384            // [32*128]                           = 4096 f
#define P_XE   20480            // [2][768]                           = 1536 f
#define P_XI   22016            // [2][256]                           =  512 f
#define P_PI   22528            // [2][32]                            =   64 f
#define P_EQ   22592            // [2][96]                            =  192 f
#define P_BE   22784            // [32]
#define P_BI   22816            // [32]
#define P_B1   22848            // [128]
#define PROJ_FLOATS 22976
#define PROJ_SMEM (PROJ_FLOATS * 4)
#define ROWS_PER_BLK 8

// =====================================================================
// Kernel P: projections (sides 0/1, 8 rows/block, weights in smem)
//           + weight prep (side 2).  grid (192, 3) x 256.  (R15-proven)
// =====================================================================
__global__ __launch_bounds__(256)
void proj_kernel(const float* __restrict__ q_equi, const float* __restrict__ q_inv,
                 const float* __restrict__ k_equi, const float* __restrict__ k_inv,
                 const float* __restrict__ Wqi, const float* __restrict__ bqi,
                 const float* __restrict__ Wki, const float* __restrict__ bki,
                 const float* __restrict__ Wqe, const float* __restrict__ bqe,
                 const float* __restrict__ Wke, const float* __restrict__ bke,
                 const float* __restrict__ W1,  const float* __restrict__ b1,
                 const float* __restrict__ W2)
{
    const int side = blockIdx.y;
    const int tid  = threadIdx.x;

    if (side == 2) {
        const int idx = blockIdx.x * 256 + tid;
        if (idx < 128*36) {
            const int n = idx / 36, kq = idx % 36;
            float a = 0.f, b = 0.f;
            if (kq < 32) {
                a = W1[(size_t)(64 + 2*kq    ) * 128 + n];
                b = W1[(size_t)(64 + 2*kq + 1) * 128 + n];
            }
            g_W1h[n*36 + kq] = pack2(a, b);
        } else if (idx < 128*36 + 64*68) {
            const int j = idx - 128*36;
            const int n = j / 68, kq = j % 68;
            float a = 0.f, b = 0.f;
            if (kq < 64) {
                a = W2[(size_t)(2*kq    ) * 64 + n];
                b = W2[(size_t)(2*kq + 1) * 64 + n];
            }
            g_W2h[n*68 + kq] = pack2(a, b);
        }
        return;
    }

    extern __shared__ float ps[];
    float* sWe = ps + P_WE;
    float* sWi = ps + P_WI;
    float* sW1s = ps + P_W1S;
    float* sXE = ps + P_XE;
    float* sXI = ps + P_XI;
    float* sPI = ps + P_PI;
    float* sEQ = ps + P_EQ;
    float* sBE = ps + P_BE;
    float* sBI = ps + P_BI;
    float* sB1 = ps + P_B1;

    const float* xe = side ? k_equi : q_equi;
    const float* xi = side ? k_inv  : q_inv;
    const float* We = side ? Wke : Wqe;
    const float* be = side ? bke : bqe;
    const float* Wi = side ? Wki : Wqi;
    const float* bi = side ? bki : bqi;

    {
        float4* d = (float4*)sWe; const float4* s = (const float4*)We;
        for (int i = tid; i < 2048; i += 256) d[i] = s[i];
        d = (float4*)sWi; s = (const float4*)Wi;
        for (int i = tid; i < 2048; i += 256) d[i] = s[i];
        d = (float4*)sW1s; s = (const float4*)(W1 + (side ? 32*128 : 0));
        for (int i = tid; i < 1024; i += 256) d[i] = s[i];
        if (!side)
            for (int i = tid; i < 128; i += 256) sB1[i] = b1[i];
        if (tid < 32)       sBE[tid] = be[tid];
        else if (tid < 64)  sBI[tid - 32] = bi[tid - 32];
    }
    __syncthreads();

    const int half = tid >> 7;
    const int ltid = tid & 127;
    const int rbase = blockIdx.x * ROWS_PER_BLK;

    #pragma unroll 1
    for (int rp = 0; rp < ROWS_PER_BLK / 2; rp++) {
        const int r  = rbase + rp * 2 + half;
        const int bb = r >= 768 ? 1 : 0;
        const int n  = r - bb * 768;

        {
            const float* src = xe + (size_t)r * 768;
            #pragma unroll
            for (int i = 0; i < 6; i++) sXE[half * 768 + ltid + i * 128] = src[ltid + i * 128];
            const float* si = xi + (size_t)r * 256;
            #pragma unroll
            for (int i = 0; i < 2; i++) sXI[half * 256 + ltid + i * 128] = si[ltid + i * 128];
        }
        __syncthreads();

        if (ltid < 96) {
            const int c = ltid >> 5, m = ltid & 31;
            float a0 = sBE[m], a1 = 0.f, a2 = 0.f, a3 = 0.f;
            #pragma unroll 4
            for (int d = 0; d < 256; d += 4) {
                a0 = fmaf(sXE[half * 768 + c * 256 + d    ], sWe[(d    ) * 32 + m], a0);
                a1 = fmaf(sXE[half * 768 + c * 256 + d + 1], sWe[(d + 1) * 32 + m], a1);
                a2 = fmaf(sXE[half * 768 + c * 256 + d + 2], sWe[(d + 2) * 32 + m], a2);
                a3 = fmaf(sXE[half * 768 + c * 256 + d + 3], sWe[(d + 3) * 32 + m], a3);
            }
            sEQ[half * 96 + ltid] = (a0 + a1) + (a2 + a3);
        } else {
            const int m = ltid - 96;
            float a0 = sBI[m], a1 = 0.f, a2 = 0.f, a3 = 0.f;
            #pragma unroll 4
            for (int d = 0; d < 256; d += 4) {
                a0 = fmaf(sXI[half * 256 + d    ], sWi[(d    ) * 32 + m], a0);
                a1 = fmaf(sXI[half * 256 + d + 1], sWi[(d + 1) * 32 + m], a1);
                a2 = fmaf(sXI[half * 256 + d + 2], sWi[(d + 2) * 32 + m], a2);
                a3 = fmaf(sXI[half * 256 + d + 3], sWi[(d + 3) * 32 + m], a3);
            }
            sPI[half * 32 + m] = (a0 + a1) + (a2 + a3);
        }
        __syncthreads();

        if (side) {
            if (ltid < 48)
                g_keTh[((size_t)bb * 48 + ltid) * NK_ + n] =
                    pack2(sEQ[half * 96 + 2*ltid], sEQ[half * 96 + 2*ltid + 1]);
            if (ltid < 64) {
                float a0 = 0.f, a1 = 0.f;
                #pragma unroll
                for (int m = 0; m < 32; m++) {
                    const float kv = sPI[half * 32 + m];
                    a0 = fmaf(kv, sW1s[m * 128 + 2*ltid],     a0);
                    a1 = fmaf(kv, sW1s[m * 128 + 2*ltid + 1], a1);
                }
                g_Bkh[((size_t)bb * NK_ + n) * 64 + ltid] = pack2(a0, a1);
            }
        } else {
            if (ltid < 48)
                g_qeh[(size_t)r * 48 + ltid] =
                    pack2(sEQ[half * 96 + 2*ltid], sEQ[half * 96 + 2*ltid + 1]);
            if (ltid < 64) {
                float a0 = sB1[2*ltid], a1 = sB1[2*ltid + 1];
                #pragma unroll
                for (int m = 0; m < 32; m++) {
                    const float qv = sPI[half * 32 + m];
                    a0 = fmaf(qv, sW1s[m * 128 + 2*ltid],     a0);
                    a1 = fmaf(qv, sW1s[m * 128 + 2*ltid + 1], a1);
                }
                g_Aqh[(size_t)r * 64 + ltid] = pack2(a0, a1);
            }
        }
        __syncthreads();
    }
}

// =====================================================================
// Kernel B: pairwise kernel, warp M-tile = 32 pairs (2q x 16k).
//   CTA = 16 q-rows x 64 k-rows; 4 passes of (4q x 64k).
//   feats -> warp-private smem F (144B rows) -> ldmatrix A.
//   GEMM1 in two sequential N=64 halves (c1 64 regs each) -> a2 (64 regs).
//   GEMM2 M=32 in two sequential N=32 halves (c2 32 regs each).
// =====================================================================
__global__ __launch_bounds__(256, 2)
void pair_kernel(const float* __restrict__ b2g, float* __restrict__ out)
{
    extern __shared__ char sm[];
    __half*   sW1h  = (__half*)(sm + O_W1H);
    __half*   sW2h  = (__half*)(sm + O_W2H);
    uint32_t* sKETH = (uint32_t*)(sm + O_KETH);
    uint32_t* sBKH  = (uint32_t*)(sm + O_BKH);
    uint32_t* sAQH  = (uint32_t*)(sm + O_AQH);
    uint32_t* sQEH  = (uint32_t*)(sm + O_QEH);
    float*    sB2   = (float*)(sm + O_B2);

    const int tid = threadIdx.x;
    const int b   = blockIdx.z;
    const int k0  = blockIdx.x * 64;
    const int q0  = blockIdx.y * 16;

    // ---------------- phase 0: one-time loads ----------------
    {
        float4* d1 = (float4*)sW1h; const float4* s1 = (const float4*)g_W1h;
        for (int i = tid; i < 1152; i += 256) d1[i] = s1[i];
        float4* d2 = (float4*)sW2h; const float4* s2 = (const float4*)g_W2h;
        for (int i = tid; i < 1088; i += 256) d2[i] = s2[i];
    }
    {
        for (int i = tid; i < 768; i += 256) {
            const int row = i >> 4, c4 = i & 15;
            *(uint4*)(sKETH + row * 68 + c4 * 4) =
                *(const uint4*)(g_keTh + ((size_t)b * 48 + row) * NK_ + k0 + c4 * 4);
        }
    }
    {
        for (int i = tid; i < 1024; i += 256) {
            const int row = i >> 4, c4 = i & 15;
            *(uint4*)(sBKH + row * 68 + c4 * 4) =
                *(const uint4*)(g_Bkh + ((size_t)b * NK_ + k0 + row) * 64 + c4 * 4);
        }
    }
    {
        for (int i = tid; i < 192; i += 256)
            ((uint4*)sQEH)[i] = *(const uint4*)(g_qeh + (size_t)(b * NQ_ + q0) * 48 + i * 4);
        for (int i = tid; i < 256; i += 256)
            ((uint4*)sAQH)[i] = *(const uint4*)(g_Aqh + (size_t)(b * NQ_ + q0) * 64 + i * 4);
        if (tid >= 192 && tid < 256) sB2[tid - 192] = b2g[tid - 192];
    }
    __syncthreads();   // the ONLY CTA barrier

    // ---------------- warp/lane geometry ----------------
    const int wid = tid >> 5, lane = tid & 31;
    const int grp = lane >> 2, tig = lane & 3;
    const int kbase = (wid & 3) * 16;
    const int kk1 = kbase + grp, kk2 = kbase + grp + 8;
    const int qpair = wid >> 2;                       // 0 or 1

    const uint32_t sW1b = smem_u32(sW1h);
    const uint32_t sW2b = smem_u32(sW2h);
    const uint32_t sFw  = smem_u32(sm + O_F) + wid * 4608;   // warp-private F

    // feats lane mapping: lane = local pair p (0..31)
    const int lq = lane >> 4;                          // q-row within pair-tile
    const int lk = kbase + (lane & 15);                // k column in sKETH/sBKH

    // ldmatrix lane address components
    const int arow = lane & 15;
    const int akof = (lane >> 4) * 16;
    const int brow = (lane & 7) + ((lane >> 4) << 3);
    const int bkof = ((lane >> 3) & 1) * 16;

    // ---------------- pass loop: 4 x (4q x 64k) ----------------
    #pragma unroll 1
    for (int pass = 0; pass < 4; pass++) {
        const int qbase = pass * 4 + qpair * 2;        // warp's first q-row
        const int qrowA = qbase + 0;                   // mt=0 rows
        const int qrowB = qbase + 1;                   // mt=1 rows

        // ---- feats: one pair per lane -> warp-private F tile ----
        {
            const int qrow = qbase + lq;
            uint32_t fo[32];
            #pragma unroll
            for (int ch2m = 0; ch2m < 16; ch2m++) {
                float dx = 0.f, dy = 0.f, sx = 0.f, sy = 0.f;
                #pragma unroll
                for (int c = 0; c < 3; c++) {
                    const int ch2 = c * 16 + ch2m;
                    const float2 q2 = unpack2(sQEH[qrow * 48 + ch2]);
                    const float2 k2 = unpack2(sKETH[ch2 * 68 + lk]);
                    dx = fmaf(q2.x, k2.x, dx);
                    dy = fmaf(q2.y, k2.y, dy);
                    float e;
                    e = q2.x - k2.x; sx = fmaf(e, e, sx);
                    e = q2.y - k2.y; sy = fmaf(e, e, sy);
                }
                fo[ch2m]      = pack2(dx, dy);
                fo[16 + ch2m] = pack2(sqrt_ap(sx), sqrt_ap(sy));
            }
            #pragma unroll
            for (int j4 = 0; j4 < 8; j4++) {
                uint4 v = make_uint4(fo[4*j4], fo[4*j4+1], fo[4*j4+2], fo[4*j4+3]);
                *(uint4*)(sm + O_F + wid * 4608 + lane * 144 + j4 * 16) = v;
            }
        }
        __syncwarp();

        // ---- GEMM1 in two N=64 halves; fold each half into a2 ----
        uint32_t a2[2][8][4];
        #pragma unroll
        for (int nh = 0; nh < 2; nh++) {
            float c1[2][8][4];
            #pragma unroll
            for (int mt = 0; mt < 2; mt++)
                #pragma unroll
                for (int nt = 0; nt < 8; nt++)
                    #pragma unroll
                    for (int j = 0; j < 4; j++) c1[mt][nt][j] = 0.f;

            #pragma unroll
            for (int ks = 0; ks < 4; ks++) {
                uint32_t a[2][4];
                ldmx4(a[0], sFw + (arow)      * 144 + ks * 32 + akof);
                ldmx4(a[1], sFw + (16 + arow) * 144 + ks * 32 + akof);
                #pragma unroll
                for (int np = 0; np < 4; np++) {
                    uint32_t bb[4];
                    ldmx4(bb, sW1b + (nh * 64 + np * 16 + brow) * 144 + ks * 32 + bkof);
                    #pragma unroll
                    for (int mt = 0; mt < 2; mt++) {
                        mma16816(c1[mt][np * 2 + 0], a[mt], bb[0], bb[1]);
                        mma16816(c1[mt][np * 2 + 1], a[mt], bb[2], bb[3]);
                    }
                }
            }

            // epilogue half: +Aq +Bk, silu -> a2 k-tiles nh*4 .. nh*4+3
            #pragma unroll
            for (int kt = 0; kt < 4; kt++) {
                #pragma unroll
                for (int hnt = 0; hnt < 2; hnt++) {
                    const int nt  = kt * 2 + hnt;
                    const int f2i = nh * 32 + nt * 4 + tig;
                    const float2 bk1 = unpack2(sBKH[kk1 * 68 + f2i]);
                    const float2 bk2 = unpack2(sBKH[kk2 * 68 + f2i]);
                    #pragma unroll
                    for (int mt = 0; mt < 2; mt++) {
                        const float2 aq = unpack2(sAQH[(qbase + mt) * 64 + f2i]);
                        const float v0 = silu_f(c1[mt][nt][0] + aq.x + bk1.x);
                        const float v1 = silu_f(c1[mt][nt][1] + aq.y + bk1.y);
                        const float v2 = silu_f(c1[mt][nt][2] + aq.x + bk2.x);
                        const float v3 = silu_f(c1[mt][nt][3] + aq.y + bk2.y);
                        a2[mt][nh * 4 + kt][hnt * 2 + 0] = pack2(v0, v1);
                        a2[mt][nh * 4 + kt][hnt * 2 + 1] = pack2(v2, v3);
                    }
                }
            }
        }

        // ---- GEMM2 M=32 in two sequential N=32 halves ----
        #pragma unroll
        for (int nh2 = 0; nh2 < 2; nh2++) {
            float c2[2][4][4];
            #pragma unroll
            for (int mt = 0; mt < 2; mt++)
                #pragma unroll
                for (int nt = 0; nt < 4; nt++)
                    #pragma unroll
                    for (int j = 0; j < 4; j++) c2[mt][nt][j] = 0.f;

            #pragma unroll
            for (int ks = 0; ks < 8; ks++) {
                #pragma unroll
                for (int np = 0; np < 2; np++) {
                    uint32_t bb[4];
                    ldmx4(bb, sW2b + (nh2 * 32 + np * 16 + brow) * 272 + ks * 32 + bkof);
                    #pragma unroll
                    for (int mt = 0; mt < 2; mt++) {
                        mma16816(c2[mt][np * 2 + 0], a2[mt][ks], bb[0], bb[1]);
                        mma16816(c2[mt][np * 2 + 1], a2[mt][ks], bb[2], bb[3]);
                    }
                }
            }

            // store this N-half: +b2
            #pragma unroll
            for (int mt = 0; mt < 2; mt++) {
                const int q = q0 + qbase + mt;
                #pragma unroll
                for (int h = 0; h < 2; h++) {
                    const int kk = kbase + grp + h * 8;
                    const size_t base = ((size_t)(b * NQ_ + q) * NK_ + k0 + kk) * 64;
                    #pragma unroll
                    for (int nt = 0; nt < 4; nt++) {
                        const int f = nh2 * 32 + nt * 8 + tig * 2;
                        float2 v;
                        v.x = c2[mt][nt][h * 2 + 0] + sB2[f];
                        v.y = c2[mt][nt][h * 2 + 1] + sB2[f + 1];
                        *(float2*)&out[base + f] = v;
                    }
                }
            }
        }
        __syncwarp();   // F tile reuse next pass (warp-private)
    }
}

// =====================================================================
extern "C" void kernel_launch(void* const* d_in, const int* in_sizes, int n_in,
                              void* d_out, int out_size)
{
    (void)in_sizes; (void)n_in; (void)out_size;
    const float* q_equi = (const float*)d_in[0];
    const float* q_inv  = (const float*)d_in[1];
    const float* k_equi = (const float*)d_in[2];
    const float* k_inv  = (const float*)d_in[3];
    const float* Wqi = (const float*)d_in[4];  const float* bqi = (const float*)d_in[5];
    const float* Wki = (const float*)d_in[6];  const float* bki = (const float*)d_in[7];
    const float* Wqe = (const float*)d_in[8];  const float* bqe = (const float*)d_in[9];
    const float* Wke = (const float*)d_in[10]; const float* bke = (const float*)d_in[11];
    const float* W1  = (const float*)d_in[12]; const float* b1  = (const float*)d_in[13];
    const float* W2  = (const float*)d_in[14]; const float* b2  = (const float*)d_in[15];
    float* out = (float*)d_out;

    cudaFuncSetAttribute(proj_kernel, cudaFuncAttributeMaxDynamicSharedMemorySize, PROJ_SMEM);
    cudaFuncSetAttribute(pair_kernel, cudaFuncAttributeMaxDynamicSharedMemorySize, SMEM_TOTAL);

    proj_kernel<<<dim3(192, 3), 256, PROJ_SMEM>>>(q_equi, q_inv, k_equi, k_inv,
                                                  Wqi, bqi, Wki, bki,
                                                  Wqe, bqe, Wke, bke, W1, b1, W2);
    pair_kernel<<<dim3(NK_ / 64, NQ_ / 16, B_), 256, SMEM_TOTAL>>>(b2, out);
}